// round 1
// baseline (speedup 1.0000x reference)
#include <cuda_runtime.h>
#include <math.h>
#include <stdint.h>

#define BB 1024
#define LLN 50
#define EE 256
#define HH 256
#define H4 1024
#define NEGV (-1e9f)
#define CEXPL 10.0f

typedef unsigned long long u64;

// ---------------- device scratch (no allocations allowed) ----------------
__device__ __align__(16) float g_e_gl[(size_t)LLN * BB * HH];  // 52.4 MB
__device__ __align__(16) float g_e_pt[(size_t)LLN * BB * HH];  // 52.4 MB
__device__ __align__(16) float g_h[BB * HH];
__device__ __align__(16) float g_c[BB * HH];
__device__ __align__(16) float g_x[BB * EE];
__device__ __align__(16) float g_G1[BB * H4];
__device__ __align__(16) float g_G2[BB * H4];
__device__ __align__(16) float g_q[BB * HH];
__device__ __align__(16) float g_g[BB * HH];
__device__ unsigned char g_mask[BB * LLN];
__device__ int g_idx[BB];

// ---------------- packed fp32x2 FMA helpers (IEEE-exact, 2x FFMA tput) ----
__device__ __forceinline__ u64 pk2(float x, float y) {
    u64 r; asm("mov.b64 %0,{%1,%2};" : "=l"(r) : "f"(x), "f"(y)); return r;
}
__device__ __forceinline__ u64 pkdup(float x) {
    u64 r; asm("mov.b64 %0,{%1,%1};" : "=l"(r) : "f"(x)); return r;
}
__device__ __forceinline__ u64 ffma2(u64 a, u64 b, u64 c) {
    u64 d; asm("fma.rn.f32x2 %0,%1,%2,%3;" : "=l"(d) : "l"(a), "l"(b), "l"(c)); return d;
}
__device__ __forceinline__ float2 upk(u64 a) {
    float2 f; asm("mov.b64 {%0,%1},%2;" : "=f"(f.x), "=f"(f.y) : "l"(a)); return f;
}

// ---------------- flag-independent transcendental helpers ----------------
// abs error ~1e-7; avoids accurate-tanhf MUFU-heavy paths and fast-math surprises
__device__ __forceinline__ float my_tanh(float x) {
    float ax = fabsf(x);
    float e  = __expf(ax + ax);          // inf for large -> r = 1
    float r  = 1.f - 2.f / (e + 1.f);
    return copysignf(r, x);
}
__device__ __forceinline__ float sigm(float x) {
    return 1.f / (1.f + __expf(-x));
}

// ---------------- init: copy state, zero mask ----------------------------
__global__ void k_init(const float* __restrict__ h0, const float* __restrict__ c0,
                       const float* __restrict__ dec) {
    int i = blockIdx.x * blockDim.x + threadIdx.x;   // 1024*256 = 262144 threads
    if (i < BB * HH) { g_h[i] = h0[i]; g_c[i] = c0[i]; }
    if (i < BB * EE) { g_x[i] = dec[i]; }
    if (i < BB * LLN) { g_mask[i] = 0; }
    if (i < BB) g_idx[i] = -1;
}

// ---------------- generic NT GEMM: C[m,n] = sum_k A[m,k]*W[n,k] + bias[n] --
// blockIdx.z selects (A1,W1,b1,C1) or (A2,W2,b2,C2) -> one launch can run
// two independent GEMMs (LSTM x-part + h-part; the two e-projections).
// Requirements: M%BM==0, N%BN==0, K%BK==0, TN==4, all ptrs 16B aligned.
template <int BM, int BN, int BK, int TM>
__global__ void gemm_nt(const float* __restrict__ A1, const float* __restrict__ W1,
                        const float* __restrict__ b1,
                        const float* __restrict__ A2, const float* __restrict__ W2,
                        const float* __restrict__ b2,
                        int M, int N, int K,
                        float* __restrict__ C1, float* __restrict__ C2) {
    constexpr int TN = 4;
    constexpr int THREADS = (BM / TM) * (BN / TN);

    const float* A = A1; const float* W = W1; const float* bias = b1; float* C = C1;
    if (blockIdx.z == 1) { A = A2; W = W2; bias = b2; C = C2; }

    __shared__ __align__(16) float As[BK][BM];
    __shared__ __align__(16) float Ws[BK][BN];

    const int tid = threadIdx.x;
    const int tx  = tid % (BN / TN);
    const int ty  = tid / (BN / TN);
    const int m0  = blockIdx.y * BM;
    const int n0  = blockIdx.x * BN;

    u64 acc[TM][2];
#pragma unroll
    for (int i = 0; i < TM; i++) { acc[i][0] = pk2(0.f, 0.f); acc[i][1] = pk2(0.f, 0.f); }

    constexpr int A_LDS = BM * BK / THREADS / 4;  // float4 loads per thread
    constexpr int W_LDS = BN * BK / THREADS / 4;

    for (int k0 = 0; k0 < K; k0 += BK) {
#pragma unroll
        for (int i = 0; i < A_LDS; i++) {
            int li = tid + i * THREADS;
            int r  = li / (BK / 4);
            int c4 = li % (BK / 4);
            float4 v = *(const float4*)(A + (size_t)(m0 + r) * K + k0 + c4 * 4);
            As[c4 * 4 + 0][r] = v.x; As[c4 * 4 + 1][r] = v.y;
            As[c4 * 4 + 2][r] = v.z; As[c4 * 4 + 3][r] = v.w;
        }
#pragma unroll
        for (int i = 0; i < W_LDS; i++) {
            int li = tid + i * THREADS;
            int r  = li / (BK / 4);
            int c4 = li % (BK / 4);
            float4 v = *(const float4*)(W + (size_t)(n0 + r) * K + k0 + c4 * 4);
            Ws[c4 * 4 + 0][r] = v.x; Ws[c4 * 4 + 1][r] = v.y;
            Ws[c4 * 4 + 2][r] = v.z; Ws[c4 * 4 + 3][r] = v.w;
        }
        __syncthreads();

#pragma unroll
        for (int kk = 0; kk < BK; kk++) {
            float4 bv = *(const float4*)&Ws[kk][tx * TN];
            u64 bp0 = pk2(bv.x, bv.y);
            u64 bp1 = pk2(bv.z, bv.w);
#pragma unroll
            for (int i = 0; i < TM; i += 4) {
                float4 av = *(const float4*)&As[kk][ty * TM + i];
                u64 a0 = pkdup(av.x), a1 = pkdup(av.y), a2 = pkdup(av.z), a3 = pkdup(av.w);
                acc[i + 0][0] = ffma2(a0, bp0, acc[i + 0][0]);
                acc[i + 0][1] = ffma2(a0, bp1, acc[i + 0][1]);
                acc[i + 1][0] = ffma2(a1, bp0, acc[i + 1][0]);
                acc[i + 1][1] = ffma2(a1, bp1, acc[i + 1][1]);
                acc[i + 2][0] = ffma2(a2, bp0, acc[i + 2][0]);
                acc[i + 2][1] = ffma2(a2, bp1, acc[i + 2][1]);
                acc[i + 3][0] = ffma2(a3, bp0, acc[i + 3][0]);
                acc[i + 3][1] = ffma2(a3, bp1, acc[i + 3][1]);
            }
        }
        __syncthreads();
    }

    const int n = n0 + tx * TN;
    float bx = 0.f, by = 0.f, bz = 0.f, bw = 0.f;
    if (bias) { bx = bias[n]; by = bias[n + 1]; bz = bias[n + 2]; bw = bias[n + 3]; }
#pragma unroll
    for (int i = 0; i < TM; i++) {
        int m = m0 + ty * TM + i;
        float2 u0 = upk(acc[i][0]);
        float2 u1 = upk(acc[i][1]);
        float4 r;
        r.x = u0.x + bx; r.y = u0.y + by; r.z = u1.x + bz; r.w = u1.y + bw;
        *(float4*)(C + (size_t)m * N + n) = r;
    }
}

// ---------------- LSTM cell + mask update (prev selection) ----------------
__global__ void k_cell(int t) {
    int b = blockIdx.x, j = threadIdx.x;
    int base = b * H4;
    float gi = g_G1[base + j]          + g_G2[base + j];
    float gf = g_G1[base + HH + j]     + g_G2[base + HH + j];
    float gg = g_G1[base + 2 * HH + j] + g_G2[base + 2 * HH + j];
    float go = g_G1[base + 3 * HH + j] + g_G2[base + 3 * HH + j];
    float c  = g_c[b * HH + j];
    float c2 = sigm(gf) * c + sigm(gi) * my_tanh(gg);
    g_c[b * HH + j] = c2;
    g_h[b * HH + j] = sigm(go) * my_tanh(c2);
    if (t > 0 && j == 0) {
        int idx = g_idx[b];
        if (idx >= 0) g_mask[b * LLN + idx] = 1;
        int cnt = 0;
#pragma unroll
        for (int l = 0; l < LLN; l++) cnt += g_mask[b * LLN + l];
        if (cnt == LLN) g_mask[b * LLN + LLN - 1] = 0;  // ref's all-true reset
    }
}

// ---------------- glimpse attention: u, masked softmax, combine -----------
__global__ void k_attn_gl(const float* __restrict__ v) {
    int b = blockIdx.x;
    int tid = threadIdx.x;            // 256
    int lane = tid & 31, w = tid >> 5;
    __shared__ float qs[HH], vs[HH];
    __shared__ float sp[LLN];
    __shared__ float s_inv;
    qs[tid] = g_q[b * HH + tid];
    vs[tid] = v[tid];
    __syncthreads();

    const float* eb = g_e_gl + (size_t)b * HH;
    for (int l = w; l < LLN; l += 8) {
        const float* er = eb + (size_t)l * BB * HH;
        float s = 0.f;
#pragma unroll
        for (int ss = 0; ss < 8; ss++) {
            int k = lane + 32 * ss;
            s += my_tanh(qs[k] + er[k]) * vs[k];
        }
#pragma unroll
        for (int o = 16; o; o >>= 1) s += __shfl_xor_sync(0xffffffffu, s, o);
        if (lane == 0) sp[l] = g_mask[b * LLN + l] ? NEGV : s;
    }
    __syncthreads();
    if (tid == 0) {
        float m = -3.4e38f;
        for (int l = 0; l < LLN; l++) m = fmaxf(m, sp[l]);
        float ssum = 0.f;
        for (int l = 0; l < LLN; l++) { float e = __expf(sp[l] - m); sp[l] = e; ssum += e; }
        s_inv = 1.f / ssum;
    }
    __syncthreads();
    float inv = s_inv;
    float acc = 0.f;
#pragma unroll 10
    for (int l = 0; l < LLN; l++) acc += sp[l] * eb[(size_t)l * BB * HH + tid];
    g_g[b * HH + tid] = acc * inv;
}

// ---- pointer attention: logits, log_softmax (-> out), argmax, gather -----
__global__ void k_attn_pt(const float* __restrict__ v, const float* __restrict__ emb,
                          float* __restrict__ out, int t, int write_sel,
                          float* __restrict__ sel_out) {
    int b = blockIdx.x;
    int tid = threadIdx.x;
    int lane = tid & 31, w = tid >> 5;
    __shared__ float qs[HH], vs[HH];
    __shared__ float sp[LLN];
    __shared__ float s_lse;
    __shared__ int s_idx;
    qs[tid] = g_q[b * HH + tid];
    vs[tid] = v[tid];
    __syncthreads();

    const float* eb = g_e_pt + (size_t)b * HH;
    for (int l = w; l < LLN; l += 8) {
        const float* er = eb + (size_t)l * BB * HH;
        float s = 0.f;
#pragma unroll
        for (int ss = 0; ss < 8; ss++) {
            int k = lane + 32 * ss;
            s += my_tanh(qs[k] + er[k]) * vs[k];
        }
#pragma unroll
        for (int o = 16; o; o >>= 1) s += __shfl_xor_sync(0xffffffffu, s, o);
        if (lane == 0) sp[l] = g_mask[b * LLN + l] ? NEGV : (CEXPL * my_tanh(s));
    }
    __syncthreads();
    if (tid == 0) {
        float m = -3.4e38f; int am = 0;
        for (int l = 0; l < LLN; l++) if (sp[l] > m) { m = sp[l]; am = l; }  // first max
        float ssum = 0.f;
        for (int l = 0; l < LLN; l++) ssum += __expf(sp[l] - m);
        s_lse = m + __logf(ssum);
        s_idx = am;
    }
    __syncthreads();
    int idx = s_idx; float lse = s_lse;
    if (tid < LLN)
        out[(size_t)b * LLN * LLN + (size_t)t * LLN + tid] = sp[tid] - lse;
    // gather next decoder input: embedded_inputs[idx, b, :]
    g_x[b * EE + tid] = emb[((size_t)idx * BB + b) * EE + tid];
    if (tid == 0) {
        g_idx[b] = idx;
        if (write_sel) sel_out[b * LLN + t] = (float)idx;
    }
}

// -------------------------------- launch ----------------------------------
extern "C" void kernel_launch(void* const* d_in, const int* in_sizes, int n_in,
                              void* d_out, int out_size) {
    (void)in_sizes; (void)n_in;
    const float* dec  = (const float*)d_in[0];
    const float* emb  = (const float*)d_in[1];
    const float* h0   = (const float*)d_in[2];
    const float* c0   = (const float*)d_in[3];
    const float* ctx  = (const float*)d_in[4];
    // d_in[5] init_mask: all-zero by construction; g_mask zeroed in k_init
    const float* Wih  = (const float*)d_in[6];
    const float* Whh  = (const float*)d_in[7];
    const float* bih  = (const float*)d_in[8];
    const float* bhh  = (const float*)d_in[9];
    const float* glWq = (const float*)d_in[10];
    const float* glbq = (const float*)d_in[11];
    const float* glWr = (const float*)d_in[12];
    const float* glbr = (const float*)d_in[13];
    const float* glv  = (const float*)d_in[14];
    const float* ptWq = (const float*)d_in[15];
    const float* ptbq = (const float*)d_in[16];
    const float* ptWr = (const float*)d_in[17];
    const float* ptbr = (const float*)d_in[18];
    const float* ptv  = (const float*)d_in[19];
    float* out = (float*)d_out;

    float *pe_gl, *pe_pt, *ph, *px, *pG1, *pG2, *pq, *pg;
    cudaGetSymbolAddress((void**)&pe_gl, g_e_gl);
    cudaGetSymbolAddress((void**)&pe_pt, g_e_pt);
    cudaGetSymbolAddress((void**)&ph,    g_h);
    cudaGetSymbolAddress((void**)&px,    g_x);
    cudaGetSymbolAddress((void**)&pG1,   g_G1);
    cudaGetSymbolAddress((void**)&pG2,   g_G2);
    cudaGetSymbolAddress((void**)&pq,    g_q);
    cudaGetSymbolAddress((void**)&pg,    g_g);

    k_init<<<1024, 256>>>(h0, c0, dec);

    // Time-invariant ref projections for BOTH attentions, one launch (z=2):
    // e[l,b,o] = sum_h ctx[l,b,h]*Wref[o,h] + bref[o]
    {
        dim3 g(HH / 64, (LLN * BB) / 128, 2);
        gemm_nt<128, 64, 16, 8><<<g, 256>>>(ctx, glWr, glbr, ctx, ptWr, ptbr,
                                            LLN * BB, HH, HH, pe_gl, pe_pt);
    }

    const size_t BLLL = (size_t)BB * LLN * LLN;
    const int wsel = (out_size >= (int)(BLLL + (size_t)BB * LLN)) ? 1 : 0;

    for (int t = 0; t < LLN; t++) {
        // LSTM gates: z=0 -> x@Wih^T + bih, z=1 -> h@Whh^T + bhh
        {
            dim3 g(H4 / 64, BB / 128, 2);
            gemm_nt<128, 64, 16, 8><<<g, 256>>>(px, Wih, bih, ph, Whh, bhh,
                                                BB, H4, HH, pG1, pG2);
        }
        k_cell<<<BB, HH>>>(t);
        // q_gl = h @ glWq^T + glbq
        {
            dim3 g(HH / 64, BB / 64, 1);
            gemm_nt<64, 64, 16, 4><<<g, 256>>>(ph, glWq, glbq, nullptr, nullptr, nullptr,
                                               BB, HH, HH, pq, nullptr);
        }
        k_attn_gl<<<BB, HH>>>(glv);
        // q_pt = g @ ptWq^T + ptbq
        {
            dim3 g(HH / 64, BB / 64, 1);
            gemm_nt<64, 64, 16, 4><<<g, 256>>>(pg, ptWq, ptbq, nullptr, nullptr, nullptr,
                                               BB, HH, HH, pq, nullptr);
        }
        k_attn_pt<<<BB, HH>>>(ptv, emb, out, t, wsel, out + BLLL);
    }
}

// round 2
// speedup vs baseline: 1.6911x; 1.6911x over previous
#include <cuda_runtime.h>
#include <math.h>
#include <float.h>

#define BB 1024
#define LLN 50
#define EE 256
#define HH 256
#define KK2 512          // E + H
#define H4 1024
#define NEGV (-1e9f)
#define CEXPL 10.0f

typedef unsigned long long u64;

// ---------------- device scratch (no allocations allowed) ----------------
__device__ __align__(16) float g_e_gl[(size_t)LLN * BB * HH];  // 52.4 MB
__device__ __align__(16) float g_e_pt[(size_t)LLN * BB * HH];  // 52.4 MB
__device__ __align__(16) float g_E2 [(size_t)LLN * BB * HH];   // 52.4 MB
__device__ __align__(16) float g_xh0[BB * KK2];                // [x | h] ping
__device__ __align__(16) float g_xh1[BB * KK2];                // [x | h] pong
__device__ __align__(16) float g_c  [BB * HH];
__device__ __align__(16) float g_qgl[BB * HH];
__device__ __align__(16) float g_qpt[BB * HH];
__device__ __align__(16) float g_Wc [H4 * KK2];                // gate-interleaved [Wih|Whh]
__device__ __align__(16) float g_bc [H4];
__device__ __align__(16) float g_Wc2[HH * HH];                 // ptWq @ glWr
__device__ __align__(16) float g_bc2[HH];
__device__ unsigned char g_mask[BB * LLN];

// ---------------- packed fp32x2 FMA helpers (IEEE-exact) ------------------
__device__ __forceinline__ u64 pk2(float x, float y) {
    u64 r; asm("mov.b64 %0,{%1,%2};" : "=l"(r) : "f"(x), "f"(y)); return r;
}
__device__ __forceinline__ u64 pkdup(float x) {
    u64 r; asm("mov.b64 %0,{%1,%1};" : "=l"(r) : "f"(x)); return r;
}
__device__ __forceinline__ u64 ffma2(u64 a, u64 b, u64 c) {
    u64 d; asm("fma.rn.f32x2 %0,%1,%2,%3;" : "=l"(d) : "l"(a), "l"(b), "l"(c)); return d;
}
__device__ __forceinline__ float2 upk(u64 a) {
    float2 f; asm("mov.b64 {%0,%1},%2;" : "=f"(f.x), "=f"(f.y) : "l"(a)); return f;
}

// ---------------- fast transcendental (err ~1e-7; we have 1e-3 budget) ----
__device__ __forceinline__ float fast_tanh(float x) {
    float ax = fabsf(x);
    float e  = __expf(ax + ax);                 // inf for big ax -> r = 1
    float r  = 1.f - __fdividef(2.f, e + 1.f);  // rcp.approx, no IEEE div
    return copysignf(r, x);
}
__device__ __forceinline__ float sigm(float x) {
    return __fdividef(1.f, 1.f + __expf(-x));
}

// ---------------- init ---------------------------------------------------
__global__ void k_init(const float* __restrict__ dec, const float* __restrict__ h0,
                       const float* __restrict__ c0) {
    int i = blockIdx.x * blockDim.x + threadIdx.x;  // 2048*256 = 524288
    if (i < BB * KK2) {
        int b = i >> 9, k = i & 511;
        g_xh0[i] = (k < EE) ? dec[b * EE + k] : h0[b * HH + (k - EE)];
    }
    if (i < BB * HH)  g_c[i] = c0[i];
    if (i < BB * LLN) g_mask[i] = 0;
}

// ---------------- weight prep (one-time) ----------------------------------
// Wc row (4j+g) <- [Wih | Whh] row (g*256+j); bc = bih+bhh (same perm)
__global__ void k_prep_lstm(const float* __restrict__ Wih, const float* __restrict__ Whh,
                            const float* __restrict__ bih, const float* __restrict__ bhh) {
    int r = blockIdx.x;                 // dest row 0..1023
    int j = r >> 2, g = r & 3;
    int src = g * HH + j;
    for (int k = threadIdx.x; k < EE; k += blockDim.x)
        g_Wc[(size_t)r * KK2 + k] = Wih[(size_t)src * EE + k];
    for (int k = threadIdx.x; k < HH; k += blockDim.x)
        g_Wc[(size_t)r * KK2 + EE + k] = Whh[(size_t)src * HH + k];
    if (threadIdx.x == 0) g_bc[r] = bih[src] + bhh[src];
}

// Wc2[j,h] = sum_o ptWq[j,o]*glWr[o,h];  bc2[j] = ptbq[j] + sum_o ptWq[j,o]*glbr[o]
__global__ void k_prep_wc2(const float* __restrict__ ptWq, const float* __restrict__ ptbq,
                           const float* __restrict__ glWr, const float* __restrict__ glbr) {
    int j = blockIdx.x, h = threadIdx.x;
    __shared__ float a[HH];
    a[h] = ptWq[(size_t)j * HH + h];
    __syncthreads();
    float s = 0.f;
#pragma unroll 8
    for (int o = 0; o < HH; o++) s = fmaf(a[o], glWr[(size_t)o * HH + h], s);
    g_Wc2[(size_t)j * HH + h] = s;
    if (h == 0) {
        float b = ptbq[j];
        for (int o = 0; o < HH; o++) b = fmaf(a[o], glbr[o], b);
        g_bc2[j] = b;
    }
}

// ---------------- generic NT GEMM, up to 3 problem sets via blockIdx.z ----
struct GA { const float* A; int lda; const float* W; const float* bias; float* C; };

template <int BM, int BN, int BK, int TM>
__global__ void gemm_multi(GA a0, GA a1, GA a2, int N, int K) {
    constexpr int TN = 4;
    constexpr int THREADS = (BM / TM) * (BN / TN);

    GA g = a0;
    if (blockIdx.z == 1) g = a1;
    if (blockIdx.z == 2) g = a2;

    __shared__ __align__(16) float As[BK][BM];
    __shared__ __align__(16) float Ws[BK][BN];

    const int tid = threadIdx.x;
    const int tx  = tid % (BN / TN);
    const int ty  = tid / (BN / TN);
    const int m0  = blockIdx.y * BM;
    const int n0  = blockIdx.x * BN;

    u64 acc[TM][2];
#pragma unroll
    for (int i = 0; i < TM; i++) { acc[i][0] = pk2(0.f, 0.f); acc[i][1] = pk2(0.f, 0.f); }

    constexpr int A_LDS = BM * BK / THREADS / 4;
    constexpr int W_LDS = BN * BK / THREADS / 4;

    for (int k0 = 0; k0 < K; k0 += BK) {
#pragma unroll
        for (int i = 0; i < A_LDS; i++) {
            int li = tid + i * THREADS;
            int r  = li / (BK / 4);
            int c4 = li % (BK / 4);
            float4 v = *(const float4*)(g.A + (size_t)(m0 + r) * g.lda + k0 + c4 * 4);
            As[c4 * 4 + 0][r] = v.x; As[c4 * 4 + 1][r] = v.y;
            As[c4 * 4 + 2][r] = v.z; As[c4 * 4 + 3][r] = v.w;
        }
#pragma unroll
        for (int i = 0; i < W_LDS; i++) {
            int li = tid + i * THREADS;
            int r  = li / (BK / 4);
            int c4 = li % (BK / 4);
            float4 v = *(const float4*)(g.W + (size_t)(n0 + r) * K + k0 + c4 * 4);
            Ws[c4 * 4 + 0][r] = v.x; Ws[c4 * 4 + 1][r] = v.y;
            Ws[c4 * 4 + 2][r] = v.z; Ws[c4 * 4 + 3][r] = v.w;
        }
        __syncthreads();

#pragma unroll
        for (int kk = 0; kk < BK; kk++) {
            float4 bv = *(const float4*)&Ws[kk][tx * TN];
            u64 bp0 = pk2(bv.x, bv.y);
            u64 bp1 = pk2(bv.z, bv.w);
#pragma unroll
            for (int i = 0; i < TM; i += 4) {
                float4 av = *(const float4*)&As[kk][ty * TM + i];
                u64 q0 = pkdup(av.x), q1 = pkdup(av.y), q2 = pkdup(av.z), q3 = pkdup(av.w);
                acc[i + 0][0] = ffma2(q0, bp0, acc[i + 0][0]);
                acc[i + 0][1] = ffma2(q0, bp1, acc[i + 0][1]);
                acc[i + 1][0] = ffma2(q1, bp0, acc[i + 1][0]);
                acc[i + 1][1] = ffma2(q1, bp1, acc[i + 1][1]);
                acc[i + 2][0] = ffma2(q2, bp0, acc[i + 2][0]);
                acc[i + 2][1] = ffma2(q2, bp1, acc[i + 2][1]);
                acc[i + 3][0] = ffma2(q3, bp0, acc[i + 3][0]);
                acc[i + 3][1] = ffma2(q3, bp1, acc[i + 3][1]);
            }
        }
        __syncthreads();
    }

    const int n = n0 + tx * TN;
    float bx = g.bias[n], by = g.bias[n + 1], bz = g.bias[n + 2], bw = g.bias[n + 3];
#pragma unroll
    for (int i = 0; i < TM; i++) {
        int m = m0 + ty * TM + i;
        float2 u0 = upk(acc[i][0]);
        float2 u1 = upk(acc[i][1]);
        float4 r;
        r.x = u0.x + bx; r.y = u0.y + by; r.z = u1.x + bz; r.w = u1.y + bw;
        *(float4*)(g.C + (size_t)m * N + n) = r;
    }
}

// ---------------- LSTM: gates GEMM + cell fused (gate-interleaved Wc) ------
// A = xh_cur [B, 512], Wc [1024, 512]; thread's 4 consecutive n = (i,f,g,o) of unit j.
__global__ void k_lstm(const float* __restrict__ A, float* __restrict__ xh_next) {
    constexpr int BM = 128, BN = 64, BK = 16, TM = 8;
    constexpr int THREADS = 256;

    __shared__ __align__(16) float As[BK][BM];
    __shared__ __align__(16) float Ws[BK][BN];

    const int tid = threadIdx.x;
    const int tx  = tid % 16;           // BN/4
    const int ty  = tid / 16;
    const int m0  = blockIdx.y * BM;
    const int n0  = blockIdx.x * BN;

    u64 acc[TM][2];
#pragma unroll
    for (int i = 0; i < TM; i++) { acc[i][0] = pk2(0.f, 0.f); acc[i][1] = pk2(0.f, 0.f); }

    for (int k0 = 0; k0 < KK2; k0 += BK) {
#pragma unroll
        for (int i = 0; i < 2; i++) {   // A_LDS = 128*16/256/4 = 2
            int li = tid + i * THREADS;
            int r  = li / 4, c4 = li % 4;
            float4 v = *(const float4*)(A + (size_t)(m0 + r) * KK2 + k0 + c4 * 4);
            As[c4 * 4 + 0][r] = v.x; As[c4 * 4 + 1][r] = v.y;
            As[c4 * 4 + 2][r] = v.z; As[c4 * 4 + 3][r] = v.w;
        }
        {                               // W_LDS = 1
            int r = tid / 4, c4 = tid % 4;
            float4 v = *(const float4*)(g_Wc + (size_t)(n0 + r) * KK2 + k0 + c4 * 4);
            Ws[c4 * 4 + 0][r] = v.x; Ws[c4 * 4 + 1][r] = v.y;
            Ws[c4 * 4 + 2][r] = v.z; Ws[c4 * 4 + 3][r] = v.w;
        }
        __syncthreads();
#pragma unroll
        for (int kk = 0; kk < BK; kk++) {
            float4 bv = *(const float4*)&Ws[kk][tx * 4];
            u64 bp0 = pk2(bv.x, bv.y);
            u64 bp1 = pk2(bv.z, bv.w);
#pragma unroll
            for (int i = 0; i < TM; i += 4) {
                float4 av = *(const float4*)&As[kk][ty * TM + i];
                u64 q0 = pkdup(av.x), q1 = pkdup(av.y), q2 = pkdup(av.z), q3 = pkdup(av.w);
                acc[i + 0][0] = ffma2(q0, bp0, acc[i + 0][0]);
                acc[i + 0][1] = ffma2(q0, bp1, acc[i + 0][1]);
                acc[i + 1][0] = ffma2(q1, bp0, acc[i + 1][0]);
                acc[i + 1][1] = ffma2(q1, bp1, acc[i + 1][1]);
                acc[i + 2][0] = ffma2(q2, bp0, acc[i + 2][0]);
                acc[i + 2][1] = ffma2(q2, bp1, acc[i + 2][1]);
                acc[i + 3][0] = ffma2(q3, bp0, acc[i + 3][0]);
                acc[i + 3][1] = ffma2(q3, bp1, acc[i + 3][1]);
            }
        }
        __syncthreads();
    }

    const int n = n0 + tx * 4;
    const int j = n >> 2;               // hidden unit index
    float bi = g_bc[n], bf = g_bc[n + 1], bg = g_bc[n + 2], bo = g_bc[n + 3];
#pragma unroll
    for (int i = 0; i < TM; i++) {
        int m = m0 + ty * TM + i;
        float2 u0 = upk(acc[i][0]);
        float2 u1 = upk(acc[i][1]);
        float gi = u0.x + bi, gf = u0.y + bf, gg = u1.x + bg, go = u1.y + bo;
        float c  = g_c[(size_t)m * HH + j];
        float c2 = sigm(gf) * c + sigm(gi) * fast_tanh(gg);
        g_c[(size_t)m * HH + j] = c2;
        xh_next[(size_t)m * KK2 + EE + j] = sigm(go) * fast_tanh(c2);
    }
}

// ---------------- glimpse attention -> q_pt --------------------------------
__global__ void k_attn_gl(const float* __restrict__ v) {
    int b = blockIdx.x, tid = threadIdx.x, lane = tid & 31, w = tid >> 5;
    __shared__ __align__(16) float qs[HH], vs[HH];
    __shared__ float sp[LLN];
    __shared__ float s_inv;
    qs[tid] = g_qgl[(size_t)b * HH + tid];
    vs[tid] = v[tid];
    __syncthreads();

    const float* eb = g_e_gl + (size_t)b * HH;
    const float4* q4 = (const float4*)qs;
    const float4* v4 = (const float4*)vs;
    for (int l = w; l < LLN; l += 8) {
        const float4* er = (const float4*)(eb + (size_t)l * BB * HH);
        float4 e0 = er[lane * 2], e1 = er[lane * 2 + 1];
        float4 q0 = q4[lane * 2], q1 = q4[lane * 2 + 1];
        float4 vv0 = v4[lane * 2], vv1 = v4[lane * 2 + 1];
        float s = fast_tanh(q0.x + e0.x) * vv0.x + fast_tanh(q0.y + e0.y) * vv0.y
                + fast_tanh(q0.z + e0.z) * vv0.z + fast_tanh(q0.w + e0.w) * vv0.w
                + fast_tanh(q1.x + e1.x) * vv1.x + fast_tanh(q1.y + e1.y) * vv1.y
                + fast_tanh(q1.z + e1.z) * vv1.z + fast_tanh(q1.w + e1.w) * vv1.w;
#pragma unroll
        for (int o = 16; o; o >>= 1) s += __shfl_xor_sync(0xffffffffu, s, o);
        if (lane == 0) sp[l] = g_mask[b * LLN + l] ? NEGV : s;
    }
    __syncthreads();
    if (w == 0) {
        float a  = (lane < LLN) ? sp[lane] : -FLT_MAX;
        float bb = (lane + 32 < LLN) ? sp[lane + 32] : -FLT_MAX;
        float m = fmaxf(a, bb);
#pragma unroll
        for (int o = 16; o; o >>= 1) m = fmaxf(m, __shfl_xor_sync(0xffffffffu, m, o));
        float ea = (lane < LLN) ? __expf(a - m) : 0.f;
        float eb2 = (lane + 32 < LLN) ? __expf(bb - m) : 0.f;
        if (lane < LLN) sp[lane] = ea;
        if (lane + 32 < LLN) sp[lane + 32] = eb2;
        float s = ea + eb2;
#pragma unroll
        for (int o = 16; o; o >>= 1) s += __shfl_xor_sync(0xffffffffu, s, o);
        if (lane == 0) s_inv = __fdividef(1.f, s);
    }
    __syncthreads();
    float inv = s_inv;
    float acc = 0.f;
    const float* E2b = g_E2 + (size_t)b * HH + tid;
#pragma unroll 10
    for (int l = 0; l < LLN; l++) acc = fmaf(sp[l], E2b[(size_t)l * BB * HH], acc);
    g_qpt[(size_t)b * HH + tid] = acc * inv;    // = q_pt (bias folded into E2)
}

// ---------------- pointer attention: log_softmax, argmax, gather, mask -----
__global__ void k_attn_pt(const float* __restrict__ v, const float* __restrict__ emb,
                          float* __restrict__ out, float* __restrict__ sel_out,
                          int t, int wsel, float* __restrict__ xh_next) {
    int b = blockIdx.x, tid = threadIdx.x, lane = tid & 31, w = tid >> 5;
    __shared__ __align__(16) float qs[HH], vs[HH];
    __shared__ float sp[LLN];
    __shared__ float s_lse;
    __shared__ int s_idx;
    qs[tid] = g_qpt[(size_t)b * HH + tid];
    vs[tid] = v[tid];
    __syncthreads();

    const float* eb = g_e_pt + (size_t)b * HH;
    const float4* q4 = (const float4*)qs;
    const float4* v4 = (const float4*)vs;
    for (int l = w; l < LLN; l += 8) {
        const float4* er = (const float4*)(eb + (size_t)l * BB * HH);
        float4 e0 = er[lane * 2], e1 = er[lane * 2 + 1];
        float4 q0 = q4[lane * 2], q1 = q4[lane * 2 + 1];
        float4 vv0 = v4[lane * 2], vv1 = v4[lane * 2 + 1];
        float s = fast_tanh(q0.x + e0.x) * vv0.x + fast_tanh(q0.y + e0.y) * vv0.y
                + fast_tanh(q0.z + e0.z) * vv0.z + fast_tanh(q0.w + e0.w) * vv0.w
                + fast_tanh(q1.x + e1.x) * vv1.x + fast_tanh(q1.y + e1.y) * vv1.y
                + fast_tanh(q1.z + e1.z) * vv1.z + fast_tanh(q1.w + e1.w) * vv1.w;
#pragma unroll
        for (int o = 16; o; o >>= 1) s += __shfl_xor_sync(0xffffffffu, s, o);
        if (lane == 0) sp[l] = g_mask[b * LLN + l] ? NEGV : (CEXPL * fast_tanh(s));
    }
    __syncthreads();
    if (w == 0) {
        float a  = (lane < LLN) ? sp[lane] : -FLT_MAX;       int ia = lane;
        float bb = (lane + 32 < LLN) ? sp[lane + 32] : -FLT_MAX; int ib = lane + 32;
        float m; int mi;
        if (bb > a) { m = bb; mi = ib; } else { m = a; mi = ia; }
#pragma unroll
        for (int o = 16; o; o >>= 1) {
            float om = __shfl_xor_sync(0xffffffffu, m, o);
            int   oi = __shfl_xor_sync(0xffffffffu, mi, o);
            if (om > m || (om == m && oi < mi)) { m = om; mi = oi; }
        }
        float s = ((lane < LLN) ? __expf(a - m) : 0.f)
                + ((lane + 32 < LLN) ? __expf(bb - m) : 0.f);
#pragma unroll
        for (int o = 16; o; o >>= 1) s += __shfl_xor_sync(0xffffffffu, s, o);
        if (lane == 0) { s_lse = m + __logf(s); s_idx = mi; }
    }
    __syncthreads();
    int idx = s_idx; float lse = s_lse;
    if (tid < LLN)
        out[((size_t)b * LLN + t) * LLN + tid] = sp[tid] - lse;
    // gather next x: embedded_inputs[idx, b, :]
    xh_next[(size_t)b * KK2 + tid] = emb[((size_t)idx * BB + b) * EE + tid];
    if (tid == 0) {
        g_mask[b * LLN + idx] = 1;       // update mask for NEXT step's logit_mask
        int cnt = 0;
#pragma unroll
        for (int l = 0; l < LLN; l++) cnt += g_mask[b * LLN + l];
        if (cnt == LLN) g_mask[b * LLN + LLN - 1] = 0;   // ref's all-true reset
        if (wsel) sel_out[b * LLN + t] = (float)idx;
    }
}

// -------------------------------- launch ----------------------------------
extern "C" void kernel_launch(void* const* d_in, const int* in_sizes, int n_in,
                              void* d_out, int out_size) {
    (void)in_sizes; (void)n_in;
    const float* dec  = (const float*)d_in[0];
    const float* emb  = (const float*)d_in[1];
    const float* h0   = (const float*)d_in[2];
    const float* c0   = (const float*)d_in[3];
    const float* ctx  = (const float*)d_in[4];
    // d_in[5] init_mask: all-zero by construction
    const float* Wih  = (const float*)d_in[6];
    const float* Whh  = (const float*)d_in[7];
    const float* bih  = (const float*)d_in[8];
    const float* bhh  = (const float*)d_in[9];
    const float* glWq = (const float*)d_in[10];
    const float* glbq = (const float*)d_in[11];
    const float* glWr = (const float*)d_in[12];
    const float* glbr = (const float*)d_in[13];
    const float* glv  = (const float*)d_in[14];
    const float* ptWq = (const float*)d_in[15];
    const float* ptbq = (const float*)d_in[16];
    const float* ptWr = (const float*)d_in[17];
    const float* ptbr = (const float*)d_in[18];
    const float* ptv  = (const float*)d_in[19];
    float* out = (float*)d_out;

    float *pe_gl, *pe_pt, *pE2, *pxh0, *pxh1, *pqgl, *pqpt, *pWc2, *pbc2;
    cudaGetSymbolAddress((void**)&pe_gl, g_e_gl);
    cudaGetSymbolAddress((void**)&pe_pt, g_e_pt);
    cudaGetSymbolAddress((void**)&pE2,   g_E2);
    cudaGetSymbolAddress((void**)&pxh0,  g_xh0);
    cudaGetSymbolAddress((void**)&pxh1,  g_xh1);
    cudaGetSymbolAddress((void**)&pqgl,  g_qgl);
    cudaGetSymbolAddress((void**)&pqpt,  g_qpt);
    cudaGetSymbolAddress((void**)&pWc2,  g_Wc2);
    cudaGetSymbolAddress((void**)&pbc2,  g_bc2);

    k_init<<<2048, 256>>>(dec, h0, c0);
    k_prep_lstm<<<H4, 256>>>(Wih, Whh, bih, bhh);
    k_prep_wc2<<<HH, HH>>>(ptWq, ptbq, glWr, glbr);

    // Time-invariant projections, all three in one z=3 launch:
    //   e_gl = ctx@glWr^T + glbr ; e_pt = ctx@ptWr^T + ptbr ; E2 = ctx@Wc2^T + bc2
    {
        GA a0{ctx, HH, glWr, glbr, pe_gl};
        GA a1{ctx, HH, ptWr, ptbr, pe_pt};
        GA a2{ctx, HH, pWc2, pbc2, pE2};
        dim3 g(HH / 64, (LLN * BB) / 128, 3);
        gemm_multi<128, 64, 16, 8><<<g, 256>>>(a0, a1, a2, HH, HH);
    }

    const size_t BLLL = (size_t)BB * LLN * LLN;
    const int wsel = (out_size >= (int)(BLLL + (size_t)BB * LLN)) ? 1 : 0;

    float* xh[2] = {pxh0, pxh1};
    for (int t = 0; t < LLN; t++) {
        float* cur = xh[t & 1];
        float* nxt = xh[(t + 1) & 1];
        // LSTM gates GEMM + fused cell: writes h_t into nxt[:,256:512], updates c
        k_lstm<<<dim3(H4 / 64, BB / 128), 256>>>(cur, nxt);
        // q_gl = h_t @ glWq^T + glbq   (A = h-part of nxt, lda = 512)
        {
            GA a{nxt + EE, KK2, glWq, glbq, pqgl};
            gemm_multi<32, 64, 16, 4><<<dim3(HH / 64, BB / 32, 1), 128>>>(a, a, a, HH, HH);
        }
        // glimpse attention -> q_pt (via precomputed E2)
        k_attn_gl<<<BB, HH>>>(glv);
        // pointer attention: log_p -> out, argmax, gather x_{t+1} into nxt, mask update
        k_attn_pt<<<BB, HH>>>(ptv, emb, out, out + BLLL, t, wsel, nxt);
    }
}